// round 4
// baseline (speedup 1.0000x reference)
#include <cuda_runtime.h>
#include <math.h>
#include <stdint.h>

#define NN 2048
#define NE 32768
#define HD 128

// ---------------- scratch ----------------
__device__ int   g_adj[NN * NN];        // winning edge index per (src,dst), -1 if none
__device__ int   g_cnt_src[NN];         // ALL out-edges per src
__device__ int   g_cnt_dst[NN];
__device__ int   g_off_src[NN + 1];
__device__ int   g_off_dst[NN + 1];
__device__ int   g_cur_src[NN];         // winner count per src (after fill)
__device__ int   g_cur_dst[NN];
__device__ int   g_nb_col[NE];          // winners: dst col
__device__ float g_nb_val[NE];          // winners: dist value
__device__ int   g_in_edge[NE];         // CSR by dst: incoming edge ids
__device__ float g_A[NN * HD];          // mu@W1_mu + sigma@W1_sig + b1
__device__ float g_res[NE];
__device__ float g_wgt[NE];
__device__ float g_wm[NE * HD];

// ---------------- 1: init (vectorized) ----------------
__global__ void __launch_bounds__(256) k_init() {
    int i = blockIdx.x * blockDim.x + threadIdx.x;           // 0 .. NN*NN/4-1
    ((int4*)g_adj)[i] = make_int4(-1, -1, -1, -1);
    if (i < NN) { g_cnt_src[i] = 0; g_cnt_dst[i] = 0; g_cur_src[i] = 0; g_cur_dst[i] = 0; }
}

// ---------------- 2: scatter (last-write-wins) + counts ----------------
__global__ void k_scatcnt(const int* __restrict__ ei) {
    int e = blockIdx.x * blockDim.x + threadIdx.x;
    if (e >= NE) return;
    int s = ei[e], d = ei[NE + e];
    atomicMax(&g_adj[s * NN + d], e);
    atomicAdd(&g_cnt_src[s], 1);
    atomicAdd(&g_cnt_dst[d], 1);
}

// ---------------- 3: parallel prefix scan (2 blocks) ----------------
__global__ void __launch_bounds__(1024) k_scan() {
    const int* in = blockIdx.x ? g_cnt_dst : g_cnt_src;
    int* off      = blockIdx.x ? g_off_dst : g_off_src;
    int t = threadIdx.x;
    int a = in[2 * t], b = in[2 * t + 1];
    int s = a + b;
    int lane = t & 31, wid = t >> 5;
    int v = s;
    #pragma unroll
    for (int o = 1; o < 32; o <<= 1) {
        int n = __shfl_up_sync(0xffffffffu, v, o);
        if (lane >= o) v += n;
    }
    __shared__ int wsum[32];
    if (lane == 31) wsum[wid] = v;
    __syncthreads();
    if (wid == 0) {
        int w = wsum[lane];
        #pragma unroll
        for (int o = 1; o < 32; o <<= 1) {
            int n = __shfl_up_sync(0xffffffffu, w, o);
            if (lane >= o) w += n;
        }
        wsum[lane] = w;
    }
    __syncthreads();
    int incl = v + (wid ? wsum[wid - 1] : 0);
    int excl = incl - s;
    off[2 * t]     = excl;
    off[2 * t + 1] = excl + a;
    if (t == 1023) off[2048] = incl;
}

// ---------------- 4: fill CSRs (winners compacted per src; all edges per dst) ----------------
__global__ void k_fill(const int* __restrict__ ei, const float* __restrict__ dist) {
    int e = blockIdx.x * blockDim.x + threadIdx.x;
    if (e >= NE) return;
    int s = ei[e], d = ei[NE + e];
    if (g_adj[s * NN + d] == e) {
        int p = atomicAdd(&g_cur_src[s], 1);
        int o = g_off_src[s] + p;
        g_nb_col[o] = d;
        g_nb_val[o] = dist[e];
    }
    int q = atomicAdd(&g_cur_dst[d], 1);
    g_in_edge[g_off_dst[d] + q] = e;
}

// ---------------- 5 (side stream): per-node layer-1 pre-GEMM ----------------
__global__ void __launch_bounds__(128) k_nodeA(const float* __restrict__ mu,
                                               const float* __restrict__ sig,
                                               const float* __restrict__ w1,
                                               const float* __restrict__ b1) {
    __shared__ float xs[16][256];
    int t = threadIdx.x;
    int nb = blockIdx.x * 16;
    #pragma unroll
    for (int i = 0; i < 16; i++) {
        xs[i][t]       = mu[(nb + i) * HD + t];
        xs[i][128 + t] = sig[(nb + i) * HD + t];
    }
    __syncthreads();
    float acc[16];
    float b = b1[t];
    #pragma unroll
    for (int i = 0; i < 16; i++) acc[i] = b;
    #pragma unroll 4
    for (int k = 0; k < 256; k++) {
        float w = __ldg(&w1[k * HD + t]);
        #pragma unroll
        for (int i = 0; i < 16; i++) acc[i] += xs[i][k] * w;
    }
    #pragma unroll
    for (int i = 0; i < 16; i++) g_A[(nb + i) * HD + t] = acc[i];
}

// ---------------- 6: residuals, warp per edge ----------------
__global__ void __launch_bounds__(256) k_res(const int* __restrict__ ei,
                                             const float* __restrict__ dist,
                                             float* __restrict__ out_res) {
    int e = blockIdx.x * 8 + (threadIdx.x >> 5);
    int lane = threadIdx.x & 31;
    int s = ei[e], d = ei[NE + e];
    int beg = g_off_src[s];
    int nw  = g_cur_src[s];              // winner count
    float sum = 0.0f; int cnt = 0;
    for (int i = lane; i < nw; i += 32) {
        int B   = g_nb_col[beg + i];
        float dab = g_nb_val[beg + i];
        int idx = g_adj[B * NN + d];
        if (idx >= 0) { sum += dab + dist[idx]; cnt++; }
    }
    #pragma unroll
    for (int o = 16; o > 0; o >>= 1) {
        sum += __shfl_down_sync(0xffffffffu, sum, o);
        cnt += __shfl_down_sync(0xffffffffu, cnt, o);
    }
    if (lane == 0) {
        float dac = dist[e];
        float mean = (cnt > 0) ? (sum / (float)cnt) : dac;
        float r = fabsf(dac - mean);
        g_res[e] = r;
        g_wgt[e] = expf(-r);
        out_res[e] = r;
    }
}

// ---------------- 7: edge hidden + tf32 mma layer-2 + weighting ----------------
#define HPAD 132
__global__ void __launch_bounds__(128) k_edge(const int* __restrict__ ei,
                                              const float* __restrict__ dist,
                                              const float* __restrict__ conf,
                                              const float* __restrict__ ang,
                                              const float* __restrict__ dep,
                                              const float* __restrict__ w1,
                                              const float* __restrict__ w2,
                                              const float* __restrict__ b2) {
    __shared__ float hid[64 * HPAD];
    int t = threadIdx.x;
    int eb = blockIdx.x * 64;

    float wf0 = w1[(256) * HD + t];
    float wf1 = w1[(257) * HD + t];
    float wf2 = w1[(258) * HD + t];
    float wf3 = w1[(259) * HD + t];
    #pragma unroll 4
    for (int x = 0; x < 64; x++) {
        int e = eb + x;
        int s = ei[e];
        float v = g_A[s * HD + t]
                + dist[e] * wf0 + conf[e] * wf1 + ang[e] * wf2 + dep[e] * wf3;
        hid[x * HPAD + t] = fmaxf(v, 0.0f);
    }
    __syncthreads();

    int warp = t >> 5;
    int lane = t & 31;
    int gid = lane >> 2;
    int tig = lane & 3;
    int n0 = warp * 32;

    float c[4][4][4];
    #pragma unroll
    for (int mt = 0; mt < 4; mt++)
        #pragma unroll
        for (int nt = 0; nt < 4; nt++)
            #pragma unroll
            for (int q = 0; q < 4; q++) c[mt][nt][q] = 0.0f;

    const uint32_t* hidu = (const uint32_t*)hid;

    #pragma unroll 2
    for (int kt = 0; kt < 16; kt++) {
        int k0 = kt * 8;
        uint32_t b0[4], b1[4];
        #pragma unroll
        for (int nt = 0; nt < 4; nt++) {
            int n = n0 + nt * 8 + gid;
            b0[nt] = __float_as_uint(__ldg(&w2[(k0 + tig) * HD + n]));
            b1[nt] = __float_as_uint(__ldg(&w2[(k0 + tig + 4) * HD + n]));
        }
        uint32_t a0[4], a1[4], a2[4], a3[4];
        #pragma unroll
        for (int mt = 0; mt < 4; mt++) {
            int r0 = mt * 16 + gid;
            a0[mt] = hidu[r0 * HPAD + k0 + tig];
            a1[mt] = hidu[(r0 + 8) * HPAD + k0 + tig];
            a2[mt] = hidu[r0 * HPAD + k0 + tig + 4];
            a3[mt] = hidu[(r0 + 8) * HPAD + k0 + tig + 4];
        }
        #pragma unroll
        for (int mt = 0; mt < 4; mt++)
            #pragma unroll
            for (int nt = 0; nt < 4; nt++) {
                asm volatile(
                    "mma.sync.aligned.m16n8k8.row.col.f32.tf32.tf32.f32 "
                    "{%0,%1,%2,%3}, {%4,%5,%6,%7}, {%8,%9}, {%0,%1,%2,%3};"
                    : "+f"(c[mt][nt][0]), "+f"(c[mt][nt][1]),
                      "+f"(c[mt][nt][2]), "+f"(c[mt][nt][3])
                    : "r"(a0[mt]), "r"(a1[mt]), "r"(a2[mt]), "r"(a3[mt]),
                      "r"(b0[nt]), "r"(b1[nt]));
            }
    }

    #pragma unroll
    for (int nt = 0; nt < 4; nt++) {
        int n = n0 + nt * 8 + 2 * tig;
        float bb0 = __ldg(&b2[n]);
        float bb1 = __ldg(&b2[n + 1]);
        #pragma unroll
        for (int mt = 0; mt < 4; mt++) {
            int e0 = eb + mt * 16 + gid;
            int e1 = e0 + 8;
            float w0 = g_wgt[e0];
            float w1v = g_wgt[e1];
            float2 v0 = make_float2((c[mt][nt][0] + bb0) * w0, (c[mt][nt][1] + bb1) * w0);
            float2 v1 = make_float2((c[mt][nt][2] + bb0) * w1v, (c[mt][nt][3] + bb1) * w1v);
            *(float2*)&g_wm[e0 * HD + n] = v0;
            *(float2*)&g_wm[e1 * HD + n] = v1;
        }
    }
}

// ---------------- 8: fused aggregation + node MLPs ----------------
__global__ void __launch_bounds__(128) k_nodeAgg(const float* __restrict__ mu,
                                              const float* __restrict__ muw1, const float* __restrict__ mub1,
                                              const float* __restrict__ muw2, const float* __restrict__ mub2,
                                              const float* __restrict__ sgw1, const float* __restrict__ sgb1,
                                              const float* __restrict__ sgw2, const float* __restrict__ sgb2,
                                              float* __restrict__ out) {
    __shared__ float xs[16][128];
    __shared__ float ys[16][128];
    __shared__ float mr[16];
    int t = threadIdx.x;
    int nb = blockIdx.x * 16;

    // aggregation (deterministic per-dst CSR walk)
    #pragma unroll 1
    for (int i = 0; i < 16; i++) {
        int n = nb + i;
        int beg = g_off_dst[n], end = g_off_dst[n + 1];
        float acc = 0.0f, ws = 0.0f, rs = 0.0f;
        for (int idx = beg; idx < end; idx++) {
            int e = g_in_edge[idx];
            acc += g_wm[e * HD + t];
            ws  += g_wgt[e];
            rs  += g_res[e];
        }
        xs[i][t] = acc / fmaxf(ws, 1e-8f);
        if (t == 0) mr[i] = rs / fmaxf((float)(end - beg), 1.0f);
    }
    __syncthreads();

    float acc[16];

    // mu hidden
    { float b = mub1[t];
      #pragma unroll
      for (int i = 0; i < 16; i++) acc[i] = b;
      #pragma unroll 4
      for (int k = 0; k < 128; k++) {
          float w = __ldg(&muw1[k * HD + t]);
          #pragma unroll
          for (int i = 0; i < 16; i++) acc[i] += xs[i][k] * w;
      } }
    #pragma unroll
    for (int i = 0; i < 16; i++) ys[i][t] = fmaxf(acc[i], 0.0f);
    __syncthreads();

    // mu out
    { float b = mub2[t];
      #pragma unroll
      for (int i = 0; i < 16; i++) acc[i] = b;
      #pragma unroll 4
      for (int k = 0; k < 128; k++) {
          float w = __ldg(&muw2[k * HD + t]);
          #pragma unroll
          for (int i = 0; i < 16; i++) acc[i] += ys[i][k] * w;
      }
      #pragma unroll
      for (int i = 0; i < 16; i++)
          out[(nb + i) * HD + t] = mu[(nb + i) * HD + t] + acc[i];
    }

    // sigma hidden (129-dim)
    { float b = sgb1[t];
      float wlast = __ldg(&sgw1[128 * HD + t]);
      #pragma unroll
      for (int i = 0; i < 16; i++) acc[i] = b + mr[i] * wlast;
      #pragma unroll 4
      for (int k = 0; k < 128; k++) {
          float w = __ldg(&sgw1[k * HD + t]);
          #pragma unroll
          for (int i = 0; i < 16; i++) acc[i] += xs[i][k] * w;
      } }
    __syncthreads();
    #pragma unroll
    for (int i = 0; i < 16; i++) ys[i][t] = fmaxf(acc[i], 0.0f);
    __syncthreads();

    // sigma out + softplus
    { float b = sgb2[t];
      #pragma unroll
      for (int i = 0; i < 16; i++) acc[i] = b;
      #pragma unroll 4
      for (int k = 0; k < 128; k++) {
          float w = __ldg(&sgw2[k * HD + t]);
          #pragma unroll
          for (int i = 0; i < 16; i++) acc[i] += ys[i][k] * w;
      }
      #pragma unroll
      for (int i = 0; i < 16; i++) {
          float x = acc[i];
          float sp = fmaxf(x, 0.0f) + log1pf(expf(-fabsf(x)));
          out[NN * HD + (nb + i) * HD + t] = sp;
      } }
}

// ---------------- launch ----------------
extern "C" void kernel_launch(void* const* d_in, const int* in_sizes, int n_in,
                              void* d_out, int out_size) {
    const float* mu    = (const float*)d_in[0];
    const float* sigma = (const float*)d_in[1];
    const int*   ei    = (const int*)d_in[2];
    const float* dist  = (const float*)d_in[3];
    const float* conf  = (const float*)d_in[4];
    const float* ang   = (const float*)d_in[5];
    const float* dep   = (const float*)d_in[6];
    const float* msgw1 = (const float*)d_in[7];
    const float* msgb1 = (const float*)d_in[8];
    const float* msgw2 = (const float*)d_in[9];
    const float* msgb2 = (const float*)d_in[10];
    const float* muw1  = (const float*)d_in[11];
    const float* mub1  = (const float*)d_in[12];
    const float* muw2  = (const float*)d_in[13];
    const float* mub2  = (const float*)d_in[14];
    const float* sgw1  = (const float*)d_in[15];
    const float* sgb1  = (const float*)d_in[16];
    const float* sgw2  = (const float*)d_in[17];
    const float* sgb2  = (const float*)d_in[18];
    float* out = (float*)d_out;
    float* out_res = out + 2 * NN * HD;

    // side stream + events (created once, before capture — first call is the
    // correctness run outside capture; same launch pattern every call)
    static cudaStream_t s_side = nullptr;
    static cudaEvent_t  s_fork = nullptr, s_join = nullptr;
    if (s_side == nullptr) {
        cudaStreamCreateWithFlags(&s_side, cudaStreamNonBlocking);
        cudaEventCreateWithFlags(&s_fork, cudaEventDisableTiming);
        cudaEventCreateWithFlags(&s_join, cudaEventDisableTiming);
    }

    k_init<<<NN * NN / 4 / 256, 256>>>();

    // fork: k_nodeA runs concurrently with the adjacency chain
    cudaEventRecord(s_fork, 0);
    cudaStreamWaitEvent(s_side, s_fork, 0);
    k_nodeA<<<NN / 16, 128, 0, s_side>>>(mu, sigma, msgw1, msgb1);
    cudaEventRecord(s_join, s_side);

    k_scatcnt<<<NE / 256, 256>>>(ei);
    k_scan<<<2, 1024>>>();
    k_fill<<<NE / 256, 256>>>(ei, dist);
    k_res<<<NE / 8, 256>>>(ei, dist, out_res);

    // join before k_edge (needs g_A)
    cudaStreamWaitEvent(0, s_join, 0);
    k_edge<<<NE / 64, 128>>>(ei, dist, conf, ang, dep, msgw1, msgw2, msgb2);
    k_nodeAgg<<<NN / 16, 128>>>(mu, muw1, mub1, muw2, mub2, sgw1, sgb1, sgw2, sgb2, out);
}

// round 5
// speedup vs baseline: 1.2642x; 1.2642x over previous
#include <cuda_runtime.h>
#include <math.h>
#include <stdint.h>

#define NN 2048
#define NE 32768
#define HD 128

// ---------------- scratch (zero-initialized at module load; every call
// restores all touched entries to zero => deterministic across replays) ----
__device__ int   g_adj[NN * NN];        // winning (edge+1) per (src,dst), 0 = none
__device__ int   g_cnt_src[NN];
__device__ int   g_cnt_dst[NN];
__device__ int   g_off_src[NN + 1];     // recomputed every call before use
__device__ int   g_off_dst[NN + 1];
__device__ int   g_cur_src[NN];         // winner count per src after fill
__device__ int   g_cur_dst[NN];
__device__ int   g_nb_col[NE];
__device__ float g_nb_val[NE];
__device__ int   g_in_edge[NE];
__device__ float g_A[NN * HD];
__device__ float g_res[NE];
__device__ float g_wgt[NE];
__device__ float g_wm[NE * HD];
__device__ float g_agg[NN * HD];
__device__ float g_meanr[NN];

// ---------------- 1: scatter (last-write-wins via max(e+1)) + degree counts ----------------
__global__ void k_scatcnt(const int* __restrict__ ei) {
    int e = blockIdx.x * blockDim.x + threadIdx.x;
    if (e >= NE) return;
    int s = ei[e], d = ei[NE + e];
    atomicMax(&g_adj[s * NN + d], e + 1);
    atomicAdd(&g_cnt_src[s], 1);
    atomicAdd(&g_cnt_dst[d], 1);
}

// ---------------- 2: parallel prefix scan (2 blocks: src + dst) ----------------
__global__ void __launch_bounds__(1024) k_scan() {
    const int* in = blockIdx.x ? g_cnt_dst : g_cnt_src;
    int* off      = blockIdx.x ? g_off_dst : g_off_src;
    int t = threadIdx.x;
    int a = in[2 * t], b = in[2 * t + 1];
    int s = a + b;
    int lane = t & 31, wid = t >> 5;
    int v = s;
    #pragma unroll
    for (int o = 1; o < 32; o <<= 1) {
        int n = __shfl_up_sync(0xffffffffu, v, o);
        if (lane >= o) v += n;
    }
    __shared__ int wsum[32];
    if (lane == 31) wsum[wid] = v;
    __syncthreads();
    if (wid == 0) {
        int w = wsum[lane];
        #pragma unroll
        for (int o = 1; o < 32; o <<= 1) {
            int n = __shfl_up_sync(0xffffffffu, w, o);
            if (lane >= o) w += n;
        }
        wsum[lane] = w;
    }
    __syncthreads();
    int incl = v + (wid ? wsum[wid - 1] : 0);
    int excl = incl - s;
    off[2 * t]     = excl;
    off[2 * t + 1] = excl + a;
    if (t == 1023) off[2048] = incl;
}

// ---------------- 3: fill CSRs (winners compacted per src; all edges per dst) ----------------
__global__ void k_fill(const int* __restrict__ ei, const float* __restrict__ dist) {
    int e = blockIdx.x * blockDim.x + threadIdx.x;
    if (e >= NE) return;
    int s = ei[e], d = ei[NE + e];
    if (g_adj[s * NN + d] == e + 1) {
        int p = atomicAdd(&g_cur_src[s], 1);
        int o = g_off_src[s] + p;
        g_nb_col[o] = d;
        g_nb_val[o] = dist[e];
    }
    int q = atomicAdd(&g_cur_dst[d], 1);
    g_in_edge[g_off_dst[d] + q] = e;
}

// ---------------- 4 (side stream): per-node layer-1 pre-GEMM ----------------
__global__ void __launch_bounds__(128) k_nodeA(const float* __restrict__ mu,
                                               const float* __restrict__ sig,
                                               const float* __restrict__ w1,
                                               const float* __restrict__ b1) {
    __shared__ float xs[16][256];
    int t = threadIdx.x;
    int nb = blockIdx.x * 16;
    #pragma unroll
    for (int i = 0; i < 16; i++) {
        xs[i][t]       = mu[(nb + i) * HD + t];
        xs[i][128 + t] = sig[(nb + i) * HD + t];
    }
    __syncthreads();
    float acc[16];
    float b = b1[t];
    #pragma unroll
    for (int i = 0; i < 16; i++) acc[i] = b;
    #pragma unroll 4
    for (int k = 0; k < 256; k++) {
        float w = __ldg(&w1[k * HD + t]);
        #pragma unroll
        for (int i = 0; i < 16; i++) acc[i] += xs[i][k] * w;
    }
    #pragma unroll
    for (int i = 0; i < 16; i++) g_A[(nb + i) * HD + t] = acc[i];
}

// ---------------- 5: residuals, warp per edge ----------------
__global__ void __launch_bounds__(256) k_res(const int* __restrict__ ei,
                                             const float* __restrict__ dist,
                                             float* __restrict__ out_res) {
    int e = blockIdx.x * 8 + (threadIdx.x >> 5);
    int lane = threadIdx.x & 31;
    int s = ei[e], d = ei[NE + e];
    int beg = g_off_src[s];
    int nw  = g_cur_src[s];
    float sum = 0.0f; int cnt = 0;
    for (int i = lane; i < nw; i += 32) {
        int B   = g_nb_col[beg + i];
        float dab = g_nb_val[beg + i];
        int idx = g_adj[B * NN + d];
        if (idx > 0) { sum += dab + dist[idx - 1]; cnt++; }
    }
    #pragma unroll
    for (int o = 16; o > 0; o >>= 1) {
        sum += __shfl_down_sync(0xffffffffu, sum, o);
        cnt += __shfl_down_sync(0xffffffffu, cnt, o);
    }
    if (lane == 0) {
        float dac = dist[e];
        float mean = (cnt > 0) ? (sum / (float)cnt) : dac;
        float r = fabsf(dac - mean);
        g_res[e] = r;
        g_wgt[e] = expf(-r);
        out_res[e] = r;
    }
}

// ---------------- 6: edge hidden + tf32 mma layer-2 + weighting + STATE CLEANUP ----------------
#define HPAD 132
__global__ void __launch_bounds__(128) k_edge(const int* __restrict__ ei,
                                              const float* __restrict__ dist,
                                              const float* __restrict__ conf,
                                              const float* __restrict__ ang,
                                              const float* __restrict__ dep,
                                              const float* __restrict__ w1,
                                              const float* __restrict__ w2,
                                              const float* __restrict__ b2) {
    __shared__ float hid[64 * HPAD];
    int t = threadIdx.x;
    int eb = blockIdx.x * 64;

    // -- cleanup: restore adj entries for this block's 64 edges to 0 (k_res is done) --
    if (t < 64) {
        int e = eb + t;
        int s = ei[e], d = ei[NE + e];
        g_adj[s * NN + d] = 0;
    }
    // -- cleanup: counter arrays (first 64 blocks cover 4 x 2048 ints) --
    if (blockIdx.x < 64) {
        int i = blockIdx.x * 128 + t;          // [0, 8192)
        if      (i < 2048) g_cnt_src[i] = 0;
        else if (i < 4096) g_cnt_dst[i - 2048] = 0;
        else if (i < 6144) g_cur_src[i - 4096] = 0;
        else               g_cur_dst[i - 6144] = 0;
    }

    // stage 1: hidden = relu(A[src] + feats @ W1_feat)
    float wf0 = w1[(256) * HD + t];
    float wf1 = w1[(257) * HD + t];
    float wf2 = w1[(258) * HD + t];
    float wf3 = w1[(259) * HD + t];
    #pragma unroll 4
    for (int x = 0; x < 64; x++) {
        int e = eb + x;
        int s = ei[e];
        float v = g_A[s * HD + t]
                + dist[e] * wf0 + conf[e] * wf1 + ang[e] * wf2 + dep[e] * wf3;
        hid[x * HPAD + t] = fmaxf(v, 0.0f);
    }
    __syncthreads();

    // stage 2: tf32 mma, warp w covers output cols [32w, 32w+32)
    int warp = t >> 5;
    int lane = t & 31;
    int gid = lane >> 2;
    int tig = lane & 3;
    int n0 = warp * 32;

    float c[4][4][4];
    #pragma unroll
    for (int mt = 0; mt < 4; mt++)
        #pragma unroll
        for (int nt = 0; nt < 4; nt++)
            #pragma unroll
            for (int q = 0; q < 4; q++) c[mt][nt][q] = 0.0f;

    const uint32_t* hidu = (const uint32_t*)hid;

    #pragma unroll 2
    for (int kt = 0; kt < 16; kt++) {
        int k0 = kt * 8;
        uint32_t b0[4], b1[4];
        #pragma unroll
        for (int nt = 0; nt < 4; nt++) {
            int n = n0 + nt * 8 + gid;
            b0[nt] = __float_as_uint(__ldg(&w2[(k0 + tig) * HD + n]));
            b1[nt] = __float_as_uint(__ldg(&w2[(k0 + tig + 4) * HD + n]));
        }
        uint32_t a0[4], a1[4], a2[4], a3[4];
        #pragma unroll
        for (int mt = 0; mt < 4; mt++) {
            int r0 = mt * 16 + gid;
            a0[mt] = hidu[r0 * HPAD + k0 + tig];
            a1[mt] = hidu[(r0 + 8) * HPAD + k0 + tig];
            a2[mt] = hidu[r0 * HPAD + k0 + tig + 4];
            a3[mt] = hidu[(r0 + 8) * HPAD + k0 + tig + 4];
        }
        #pragma unroll
        for (int mt = 0; mt < 4; mt++)
            #pragma unroll
            for (int nt = 0; nt < 4; nt++) {
                asm volatile(
                    "mma.sync.aligned.m16n8k8.row.col.f32.tf32.tf32.f32 "
                    "{%0,%1,%2,%3}, {%4,%5,%6,%7}, {%8,%9}, {%0,%1,%2,%3};"
                    : "+f"(c[mt][nt][0]), "+f"(c[mt][nt][1]),
                      "+f"(c[mt][nt][2]), "+f"(c[mt][nt][3])
                    : "r"(a0[mt]), "r"(a1[mt]), "r"(a2[mt]), "r"(a3[mt]),
                      "r"(b0[nt]), "r"(b1[nt]));
            }
    }

    #pragma unroll
    for (int nt = 0; nt < 4; nt++) {
        int n = n0 + nt * 8 + 2 * tig;
        float bb0 = __ldg(&b2[n]);
        float bb1 = __ldg(&b2[n + 1]);
        #pragma unroll
        for (int mt = 0; mt < 4; mt++) {
            int e0 = eb + mt * 16 + gid;
            int e1 = e0 + 8;
            float w0 = g_wgt[e0];
            float w1v = g_wgt[e1];
            float2 v0 = make_float2((c[mt][nt][0] + bb0) * w0, (c[mt][nt][1] + bb1) * w0);
            float2 v1 = make_float2((c[mt][nt][2] + bb0) * w1v, (c[mt][nt][3] + bb1) * w1v);
            *(float2*)&g_wm[e0 * HD + n] = v0;
            *(float2*)&g_wm[e1 * HD + n] = v1;
        }
    }
}

// ---------------- 7: deterministic segment aggregation by dst (2048 blocks) ----------------
__global__ void __launch_bounds__(128) k_agg() {
    int n = blockIdx.x;
    int t = threadIdx.x;
    int beg = g_off_dst[n], end = g_off_dst[n + 1];
    float acc = 0.0f, ws = 0.0f, rs = 0.0f;
    for (int i = beg; i < end; i++) {
        int e = g_in_edge[i];
        acc += g_wm[e * HD + t];
        ws  += g_wgt[e];
        rs  += g_res[e];
    }
    g_agg[n * HD + t] = acc / fmaxf(ws, 1e-8f);
    if (t == 0) g_meanr[n] = rs / fmaxf((float)(end - beg), 1.0f);
}

// ---------------- 8: node MLPs ----------------
__global__ void __launch_bounds__(128) k_node(const float* __restrict__ mu,
                                              const float* __restrict__ muw1, const float* __restrict__ mub1,
                                              const float* __restrict__ muw2, const float* __restrict__ mub2,
                                              const float* __restrict__ sgw1, const float* __restrict__ sgb1,
                                              const float* __restrict__ sgw2, const float* __restrict__ sgb2,
                                              float* __restrict__ out) {
    __shared__ float xs[16][128];
    __shared__ float ys[16][128];
    __shared__ float mr[16];
    int t = threadIdx.x;
    int nb = blockIdx.x * 16;
    #pragma unroll
    for (int i = 0; i < 16; i++) xs[i][t] = g_agg[(nb + i) * HD + t];
    if (t < 16) mr[t] = g_meanr[nb + t];
    __syncthreads();

    float acc[16];

    { float b = mub1[t];
      #pragma unroll
      for (int i = 0; i < 16; i++) acc[i] = b;
      #pragma unroll 4
      for (int k = 0; k < 128; k++) {
          float w = __ldg(&muw1[k * HD + t]);
          #pragma unroll
          for (int i = 0; i < 16; i++) acc[i] += xs[i][k] * w;
      } }
    #pragma unroll
    for (int i = 0; i < 16; i++) ys[i][t] = fmaxf(acc[i], 0.0f);
    __syncthreads();

    { float b = mub2[t];
      #pragma unroll
      for (int i = 0; i < 16; i++) acc[i] = b;
      #pragma unroll 4
      for (int k = 0; k < 128; k++) {
          float w = __ldg(&muw2[k * HD + t]);
          #pragma unroll
          for (int i = 0; i < 16; i++) acc[i] += ys[i][k] * w;
      }
      #pragma unroll
      for (int i = 0; i < 16; i++)
          out[(nb + i) * HD + t] = mu[(nb + i) * HD + t] + acc[i];
    }

    { float b = sgb1[t];
      float wlast = __ldg(&sgw1[128 * HD + t]);
      #pragma unroll
      for (int i = 0; i < 16; i++) acc[i] = b + mr[i] * wlast;
      #pragma unroll 4
      for (int k = 0; k < 128; k++) {
          float w = __ldg(&sgw1[k * HD + t]);
          #pragma unroll
          for (int i = 0; i < 16; i++) acc[i] += xs[i][k] * w;
      } }
    __syncthreads();
    #pragma unroll
    for (int i = 0; i < 16; i++) ys[i][t] = fmaxf(acc[i], 0.0f);
    __syncthreads();

    { float b = sgb2[t];
      #pragma unroll
      for (int i = 0; i < 16; i++) acc[i] = b;
      #pragma unroll 4
      for (int k = 0; k < 128; k++) {
          float w = __ldg(&sgw2[k * HD + t]);
          #pragma unroll
          for (int i = 0; i < 16; i++) acc[i] += ys[i][k] * w;
      }
      #pragma unroll
      for (int i = 0; i < 16; i++) {
          float x = acc[i];
          float sp = fmaxf(x, 0.0f) + log1pf(expf(-fabsf(x)));
          out[NN * HD + (nb + i) * HD + t] = sp;
      } }
}

// ---------------- launch ----------------
extern "C" void kernel_launch(void* const* d_in, const int* in_sizes, int n_in,
                              void* d_out, int out_size) {
    const float* mu    = (const float*)d_in[0];
    const float* sigma = (const float*)d_in[1];
    const int*   ei    = (const int*)d_in[2];
    const float* dist  = (const float*)d_in[3];
    const float* conf  = (const float*)d_in[4];
    const float* ang   = (const float*)d_in[5];
    const float* dep   = (const float*)d_in[6];
    const float* msgw1 = (const float*)d_in[7];
    const float* msgb1 = (const float*)d_in[8];
    const float* msgw2 = (const float*)d_in[9];
    const float* msgb2 = (const float*)d_in[10];
    const float* muw1  = (const float*)d_in[11];
    const float* mub1  = (const float*)d_in[12];
    const float* muw2  = (const float*)d_in[13];
    const float* mub2  = (const float*)d_in[14];
    const float* sgw1  = (const float*)d_in[15];
    const float* sgb1  = (const float*)d_in[16];
    const float* sgw2  = (const float*)d_in[17];
    const float* sgb2  = (const float*)d_in[18];
    float* out = (float*)d_out;
    float* out_res = out + 2 * NN * HD;

    static cudaStream_t s_side = nullptr;
    static cudaEvent_t  s_fork = nullptr, s_join = nullptr;
    if (s_side == nullptr) {
        cudaStreamCreateWithFlags(&s_side, cudaStreamNonBlocking);
        cudaEventCreateWithFlags(&s_fork, cudaEventDisableTiming);
        cudaEventCreateWithFlags(&s_join, cudaEventDisableTiming);
    }

    // fork: node pre-GEMM runs concurrently with the adjacency chain
    cudaEventRecord(s_fork, 0);
    cudaStreamWaitEvent(s_side, s_fork, 0);
    k_nodeA<<<NN / 16, 128, 0, s_side>>>(mu, sigma, msgw1, msgb1);
    cudaEventRecord(s_join, s_side);

    k_scatcnt<<<NE / 256, 256>>>(ei);
    k_scan<<<2, 1024>>>();
    k_fill<<<NE / 256, 256>>>(ei, dist);
    k_res<<<NE / 8, 256>>>(ei, dist, out_res);

    cudaStreamWaitEvent(0, s_join, 0);
    k_edge<<<NE / 64, 128>>>(ei, dist, conf, ang, dep, msgw1, msgw2, msgb2);
    k_agg<<<NN, 128>>>();
    k_node<<<NN / 16, 128>>>(mu, muw1, mub1, muw2, mub2, sgw1, sgb1, sgw2, sgb2, out);
}

// round 6
// speedup vs baseline: 1.3024x; 1.0302x over previous
#include <cuda_runtime.h>
#include <math.h>
#include <stdint.h>

#define NN 2048
#define NE 32768
#define HD 128

// ---------------- scratch (zero at module load; every call restores zeros) ----
__device__ int   g_adj[NN * NN];        // winning (edge+1) per (src,dst), 0 = none
__device__ int   g_cnt_src[NN];
__device__ int   g_cnt_dst[NN];
__device__ int   g_off_src[NN + 1];
__device__ int   g_off_dst[NN + 1];
__device__ int   g_cur_src[NN];
__device__ int   g_cur_dst[NN];
__device__ int   g_nb_col[NE];
__device__ float g_nb_val[NE];
__device__ int   g_in_edge[NE];
__device__ float g_A[NN * HD];
__device__ float g_res[NE];
__device__ float g_wgt[NE];
__device__ float g_wm[NE * HD];         // UNweighted messages now
__device__ float g_agg[NN * HD];
__device__ float g_meanr[NN];

// ---------------- chain A1: scatter + degree counts ----------------
__global__ void k_scatcnt(const int* __restrict__ ei) {
    int e = blockIdx.x * blockDim.x + threadIdx.x;
    if (e >= NE) return;
    int s = ei[e], d = ei[NE + e];
    atomicMax(&g_adj[s * NN + d], e + 1);
    atomicAdd(&g_cnt_src[s], 1);
    atomicAdd(&g_cnt_dst[d], 1);
}

// ---------------- chain A2: parallel prefix scan (2 blocks) ----------------
__global__ void __launch_bounds__(1024) k_scan() {
    const int* in = blockIdx.x ? g_cnt_dst : g_cnt_src;
    int* off      = blockIdx.x ? g_off_dst : g_off_src;
    int t = threadIdx.x;
    int a = in[2 * t], b = in[2 * t + 1];
    int s = a + b;
    int lane = t & 31, wid = t >> 5;
    int v = s;
    #pragma unroll
    for (int o = 1; o < 32; o <<= 1) {
        int n = __shfl_up_sync(0xffffffffu, v, o);
        if (lane >= o) v += n;
    }
    __shared__ int wsum[32];
    if (lane == 31) wsum[wid] = v;
    __syncthreads();
    if (wid == 0) {
        int w = wsum[lane];
        #pragma unroll
        for (int o = 1; o < 32; o <<= 1) {
            int n = __shfl_up_sync(0xffffffffu, w, o);
            if (lane >= o) w += n;
        }
        wsum[lane] = w;
    }
    __syncthreads();
    int incl = v + (wid ? wsum[wid - 1] : 0);
    int excl = incl - s;
    off[2 * t]     = excl;
    off[2 * t + 1] = excl + a;
    if (t == 1023) off[2048] = incl;
}

// ---------------- chain A3: fill CSRs ----------------
__global__ void k_fill(const int* __restrict__ ei, const float* __restrict__ dist) {
    int e = blockIdx.x * blockDim.x + threadIdx.x;
    if (e >= NE) return;
    int s = ei[e], d = ei[NE + e];
    if (g_adj[s * NN + d] == e + 1) {
        int p = atomicAdd(&g_cur_src[s], 1);
        int o = g_off_src[s] + p;
        g_nb_col[o] = d;
        g_nb_val[o] = dist[e];
    }
    int q = atomicAdd(&g_cur_dst[d], 1);
    g_in_edge[g_off_dst[d] + q] = e;
}

// ---------------- chain A4: residuals, warp per edge ----------------
__global__ void __launch_bounds__(256) k_res(const int* __restrict__ ei,
                                             const float* __restrict__ dist,
                                             float* __restrict__ out_res) {
    int e = blockIdx.x * 8 + (threadIdx.x >> 5);
    int lane = threadIdx.x & 31;
    int s = ei[e], d = ei[NE + e];
    int beg = g_off_src[s];
    int nw  = g_cur_src[s];
    float sum = 0.0f; int cnt = 0;
    for (int i = lane; i < nw; i += 32) {
        int B   = g_nb_col[beg + i];
        float dab = g_nb_val[beg + i];
        int idx = g_adj[B * NN + d];
        if (idx > 0) { sum += dab + dist[idx - 1]; cnt++; }
    }
    #pragma unroll
    for (int o = 16; o > 0; o >>= 1) {
        sum += __shfl_down_sync(0xffffffffu, sum, o);
        cnt += __shfl_down_sync(0xffffffffu, cnt, o);
    }
    if (lane == 0) {
        float dac = dist[e];
        float mean = (cnt > 0) ? (sum / (float)cnt) : dac;
        float r = fabsf(dac - mean);
        g_res[e] = r;
        g_wgt[e] = expf(-r);
        out_res[e] = r;
    }
}

// ---------------- chain B1 (side stream): per-node layer-1 pre-GEMM ----------------
__global__ void __launch_bounds__(128) k_nodeA(const float* __restrict__ mu,
                                               const float* __restrict__ sig,
                                               const float* __restrict__ w1,
                                               const float* __restrict__ b1) {
    __shared__ float xs[16][256];
    int t = threadIdx.x;
    int nb = blockIdx.x * 16;
    #pragma unroll
    for (int i = 0; i < 16; i++) {
        xs[i][t]       = mu[(nb + i) * HD + t];
        xs[i][128 + t] = sig[(nb + i) * HD + t];
    }
    __syncthreads();
    float acc[16];
    float b = b1[t];
    #pragma unroll
    for (int i = 0; i < 16; i++) acc[i] = b;
    #pragma unroll 4
    for (int k = 0; k < 256; k++) {
        float w = __ldg(&w1[k * HD + t]);
        #pragma unroll
        for (int i = 0; i < 16; i++) acc[i] += xs[i][k] * w;
    }
    #pragma unroll
    for (int i = 0; i < 16; i++) g_A[(nb + i) * HD + t] = acc[i];
}

// ---------------- chain B2 (side stream): edge hidden + tf32 mma layer-2 ----------------
// NOTE: no dependency on the adjacency chain — weighting is applied in k_agg.
#define HPAD 132
__global__ void __launch_bounds__(128) k_edge(const int* __restrict__ ei,
                                              const float* __restrict__ dist,
                                              const float* __restrict__ conf,
                                              const float* __restrict__ ang,
                                              const float* __restrict__ dep,
                                              const float* __restrict__ w1,
                                              const float* __restrict__ w2,
                                              const float* __restrict__ b2) {
    __shared__ float hid[64 * HPAD];
    int t = threadIdx.x;
    int eb = blockIdx.x * 64;

    float wf0 = w1[(256) * HD + t];
    float wf1 = w1[(257) * HD + t];
    float wf2 = w1[(258) * HD + t];
    float wf3 = w1[(259) * HD + t];
    #pragma unroll 4
    for (int x = 0; x < 64; x++) {
        int e = eb + x;
        int s = ei[e];
        float v = g_A[s * HD + t]
                + dist[e] * wf0 + conf[e] * wf1 + ang[e] * wf2 + dep[e] * wf3;
        hid[x * HPAD + t] = fmaxf(v, 0.0f);
    }
    __syncthreads();

    int warp = t >> 5;
    int lane = t & 31;
    int gid = lane >> 2;
    int tig = lane & 3;
    int n0 = warp * 32;

    float c[4][4][4];
    #pragma unroll
    for (int mt = 0; mt < 4; mt++)
        #pragma unroll
        for (int nt = 0; nt < 4; nt++)
            #pragma unroll
            for (int q = 0; q < 4; q++) c[mt][nt][q] = 0.0f;

    const uint32_t* hidu = (const uint32_t*)hid;

    #pragma unroll 2
    for (int kt = 0; kt < 16; kt++) {
        int k0 = kt * 8;
        uint32_t b0[4], b1[4];
        #pragma unroll
        for (int nt = 0; nt < 4; nt++) {
            int n = n0 + nt * 8 + gid;
            b0[nt] = __float_as_uint(__ldg(&w2[(k0 + tig) * HD + n]));
            b1[nt] = __float_as_uint(__ldg(&w2[(k0 + tig + 4) * HD + n]));
        }
        uint32_t a0[4], a1[4], a2[4], a3[4];
        #pragma unroll
        for (int mt = 0; mt < 4; mt++) {
            int r0 = mt * 16 + gid;
            a0[mt] = hidu[r0 * HPAD + k0 + tig];
            a1[mt] = hidu[(r0 + 8) * HPAD + k0 + tig];
            a2[mt] = hidu[r0 * HPAD + k0 + tig + 4];
            a3[mt] = hidu[(r0 + 8) * HPAD + k0 + tig + 4];
        }
        #pragma unroll
        for (int mt = 0; mt < 4; mt++)
            #pragma unroll
            for (int nt = 0; nt < 4; nt++) {
                asm volatile(
                    "mma.sync.aligned.m16n8k8.row.col.f32.tf32.tf32.f32 "
                    "{%0,%1,%2,%3}, {%4,%5,%6,%7}, {%8,%9}, {%0,%1,%2,%3};"
                    : "+f"(c[mt][nt][0]), "+f"(c[mt][nt][1]),
                      "+f"(c[mt][nt][2]), "+f"(c[mt][nt][3])
                    : "r"(a0[mt]), "r"(a1[mt]), "r"(a2[mt]), "r"(a3[mt]),
                      "r"(b0[nt]), "r"(b1[nt]));
            }
    }

    // epilogue: wm = C + b2  (unweighted)
    #pragma unroll
    for (int nt = 0; nt < 4; nt++) {
        int n = n0 + nt * 8 + 2 * tig;
        float bb0 = __ldg(&b2[n]);
        float bb1 = __ldg(&b2[n + 1]);
        #pragma unroll
        for (int mt = 0; mt < 4; mt++) {
            int e0 = eb + mt * 16 + gid;
            int e1 = e0 + 8;
            float2 v0 = make_float2(c[mt][nt][0] + bb0, c[mt][nt][1] + bb1);
            float2 v1 = make_float2(c[mt][nt][2] + bb0, c[mt][nt][3] + bb1);
            *(float2*)&g_wm[e0 * HD + n] = v0;
            *(float2*)&g_wm[e1 * HD + n] = v1;
        }
    }
}

// ---------------- join: aggregation (weight applied here) + state cleanup ----------------
__global__ void __launch_bounds__(128) k_agg(const int* __restrict__ ei) {
    int n = blockIdx.x;
    int t = threadIdx.x;

    // cleanup: this block resets adj entries for edges [16n, 16n+16)  (k_res done)
    if (t < 16) {
        int e = n * 16 + t;
        int s = ei[e], d = ei[NE + e];
        g_adj[s * NN + d] = 0;
    }
    // cleanup: counter arrays (first 64 blocks cover 4 x 2048 ints)
    if (n < 64) {
        int i = n * 128 + t;
        if      (i < 2048) g_cnt_src[i] = 0;
        else if (i < 4096) g_cnt_dst[i - 2048] = 0;
        else if (i < 6144) g_cur_src[i - 4096] = 0;
        else               g_cur_dst[i - 6144] = 0;
    }

    int beg = g_off_dst[n], end = g_off_dst[n + 1];
    float acc = 0.0f, ws = 0.0f, rs = 0.0f;
    for (int i = beg; i < end; i++) {
        int e = g_in_edge[i];
        float w = g_wgt[e];
        acc += g_wm[e * HD + t] * w;
        ws  += w;
        rs  += g_res[e];
    }
    g_agg[n * HD + t] = acc / fmaxf(ws, 1e-8f);
    if (t == 0) g_meanr[n] = rs / fmaxf((float)(end - beg), 1.0f);
}

// ---------------- node MLPs ----------------
__global__ void __launch_bounds__(128) k_node(const float* __restrict__ mu,
                                              const float* __restrict__ muw1, const float* __restrict__ mub1,
                                              const float* __restrict__ muw2, const float* __restrict__ mub2,
                                              const float* __restrict__ sgw1, const float* __restrict__ sgb1,
                                              const float* __restrict__ sgw2, const float* __restrict__ sgb2,
                                              float* __restrict__ out) {
    __shared__ float xs[16][128];
    __shared__ float ys[16][128];
    __shared__ float mr[16];
    int t = threadIdx.x;
    int nb = blockIdx.x * 16;
    #pragma unroll
    for (int i = 0; i < 16; i++) xs[i][t] = g_agg[(nb + i) * HD + t];
    if (t < 16) mr[t] = g_meanr[nb + t];
    __syncthreads();

    float acc[16];

    { float b = mub1[t];
      #pragma unroll
      for (int i = 0; i < 16; i++) acc[i] = b;
      #pragma unroll 4
      for (int k = 0; k < 128; k++) {
          float w = __ldg(&muw1[k * HD + t]);
          #pragma unroll
          for (int i = 0; i < 16; i++) acc[i] += xs[i][k] * w;
      } }
    #pragma unroll
    for (int i = 0; i < 16; i++) ys[i][t] = fmaxf(acc[i], 0.0f);
    __syncthreads();

    { float b = mub2[t];
      #pragma unroll
      for (int i = 0; i < 16; i++) acc[i] = b;
      #pragma unroll 4
      for (int k = 0; k < 128; k++) {
          float w = __ldg(&muw2[k * HD + t]);
          #pragma unroll
          for (int i = 0; i < 16; i++) acc[i] += ys[i][k] * w;
      }
      #pragma unroll
      for (int i = 0; i < 16; i++)
          out[(nb + i) * HD + t] = mu[(nb + i) * HD + t] + acc[i];
    }

    { float b = sgb1[t];
      float wlast = __ldg(&sgw1[128 * HD + t]);
      #pragma unroll
      for (int i = 0; i < 16; i++) acc[i] = b + mr[i] * wlast;
      #pragma unroll 4
      for (int k = 0; k < 128; k++) {
          float w = __ldg(&sgw1[k * HD + t]);
          #pragma unroll
          for (int i = 0; i < 16; i++) acc[i] += xs[i][k] * w;
      } }
    __syncthreads();
    #pragma unroll
    for (int i = 0; i < 16; i++) ys[i][t] = fmaxf(acc[i], 0.0f);
    __syncthreads();

    { float b = sgb2[t];
      #pragma unroll
      for (int i = 0; i < 16; i++) acc[i] = b;
      #pragma unroll 4
      for (int k = 0; k < 128; k++) {
          float w = __ldg(&sgw2[k * HD + t]);
          #pragma unroll
          for (int i = 0; i < 16; i++) acc[i] += ys[i][k] * w;
      }
      #pragma unroll
      for (int i = 0; i < 16; i++) {
          float x = acc[i];
          float sp = fmaxf(x, 0.0f) + log1pf(expf(-fabsf(x)));
          out[NN * HD + (nb + i) * HD + t] = sp;
      } }
}

// ---------------- launch ----------------
extern "C" void kernel_launch(void* const* d_in, const int* in_sizes, int n_in,
                              void* d_out, int out_size) {
    const float* mu    = (const float*)d_in[0];
    const float* sigma = (const float*)d_in[1];
    const int*   ei    = (const int*)d_in[2];
    const float* dist  = (const float*)d_in[3];
    const float* conf  = (const float*)d_in[4];
    const float* ang   = (const float*)d_in[5];
    const float* dep   = (const float*)d_in[6];
    const float* msgw1 = (const float*)d_in[7];
    const float* msgb1 = (const float*)d_in[8];
    const float* msgw2 = (const float*)d_in[9];
    const float* msgb2 = (const float*)d_in[10];
    const float* muw1  = (const float*)d_in[11];
    const float* mub1  = (const float*)d_in[12];
    const float* muw2  = (const float*)d_in[13];
    const float* mub2  = (const float*)d_in[14];
    const float* sgw1  = (const float*)d_in[15];
    const float* sgb1  = (const float*)d_in[16];
    const float* sgw2  = (const float*)d_in[17];
    const float* sgb2  = (const float*)d_in[18];
    float* out = (float*)d_out;
    float* out_res = out + 2 * NN * HD;

    static cudaStream_t s_side = nullptr;
    static cudaEvent_t  s_fork = nullptr, s_join = nullptr;
    if (s_side == nullptr) {
        cudaStreamCreateWithFlags(&s_side, cudaStreamNonBlocking);
        cudaEventCreateWithFlags(&s_fork, cudaEventDisableTiming);
        cudaEventCreateWithFlags(&s_join, cudaEventDisableTiming);
    }

    // fork chain B: nodeA -> edge (independent of adjacency chain)
    cudaEventRecord(s_fork, 0);
    cudaStreamWaitEvent(s_side, s_fork, 0);
    k_nodeA<<<NN / 16, 128, 0, s_side>>>(mu, sigma, msgw1, msgb1);
    k_edge<<<NE / 64, 128, 0, s_side>>>(ei, dist, conf, ang, dep, msgw1, msgw2, msgb2);
    cudaEventRecord(s_join, s_side);

    // chain A: adjacency / residuals
    k_scatcnt<<<NE / 256, 256>>>(ei);
    k_scan<<<2, 1024>>>();
    k_fill<<<NE / 256, 256>>>(ei, dist);
    k_res<<<NE / 8, 256>>>(ei, dist, out_res);

    // join, then aggregate + node MLPs
    cudaStreamWaitEvent(0, s_join, 0);
    k_agg<<<NN, 128>>>(ei);
    k_node<<<NN / 16, 128>>>(mu, muw1, mub1, muw2, mub2, sgw1, sgb1, sgw2, sgb2, out);
}

// round 7
// speedup vs baseline: 1.3104x; 1.0062x over previous
#include <cuda_runtime.h>
#include <math.h>
#include <stdint.h>

#define NN 2048
#define NE 32768
#define HD 128
#define CAP 128   // bucket capacity per node (max in/out degree; binomial mean 16)

// ---------------- scratch (zero at module load; every call restores zeros) ----
__device__ int   g_adj[NN * NN];          // winning (edge+1) per (src,dst), 0 = none
__device__ int   g_wcnt_src[NN];          // winner (dedup'd) out-degree
__device__ int   g_cnt_dst[NN];           // in-degree
__device__ int   g_nb_col[NN * CAP];      // src bucket: dedup'd out-neighbor col
__device__ float g_nb_val[NN * CAP];      // src bucket: winner dist
__device__ int   g_in_edge[NN * CAP];     // dst bucket: incoming edge ids
__device__ float g_A[NN * HD];
__device__ float g_res[NE];
__device__ float g_wgt[NE];
__device__ float g_wm[NE * HD];           // unweighted messages
__device__ float g_agg[NN * HD];
__device__ float g_meanr[NN];

// ---------------- chain A1: adj scatter + dst bucket fill ----------------
__global__ void k_scatcnt(const int* __restrict__ ei) {
    int e = blockIdx.x * blockDim.x + threadIdx.x;
    if (e >= NE) return;
    int s = ei[e], d = ei[NE + e];
    atomicMax(&g_adj[s * NN + d], e + 1);
    int q = atomicAdd(&g_cnt_dst[d], 1);
    g_in_edge[d * CAP + q] = e;
}

// ---------------- chain A2: src winner bucket fill ----------------
__global__ void k_fill(const int* __restrict__ ei, const float* __restrict__ dist) {
    int e = blockIdx.x * blockDim.x + threadIdx.x;
    if (e >= NE) return;
    int s = ei[e], d = ei[NE + e];
    if (g_adj[s * NN + d] == e + 1) {
        int p = atomicAdd(&g_wcnt_src[s], 1);
        g_nb_col[s * CAP + p] = d;
        g_nb_val[s * CAP + p] = dist[e];
    }
}

// ---------------- chain A3: residuals, warp per edge ----------------
__global__ void __launch_bounds__(256) k_res(const int* __restrict__ ei,
                                             const float* __restrict__ dist,
                                             float* __restrict__ out_res) {
    int e = blockIdx.x * 8 + (threadIdx.x >> 5);
    int lane = threadIdx.x & 31;
    int s = ei[e], d = ei[NE + e];
    int nw = g_wcnt_src[s];
    int base = s * CAP;
    float sum = 0.0f; int cnt = 0;
    for (int i = lane; i < nw; i += 32) {
        int B   = g_nb_col[base + i];
        float dab = g_nb_val[base + i];
        int idx = g_adj[B * NN + d];
        if (idx > 0) { sum += dab + dist[idx - 1]; cnt++; }
    }
    #pragma unroll
    for (int o = 16; o > 0; o >>= 1) {
        sum += __shfl_down_sync(0xffffffffu, sum, o);
        cnt += __shfl_down_sync(0xffffffffu, cnt, o);
    }
    if (lane == 0) {
        float dac = dist[e];
        float mean = (cnt > 0) ? (sum / (float)cnt) : dac;
        float r = fabsf(dac - mean);
        g_res[e] = r;
        g_wgt[e] = expf(-r);
        out_res[e] = r;
    }
}

// ---------------- chain B1 (side stream): per-node layer-1 pre-GEMM ----------------
__global__ void __launch_bounds__(128) k_nodeA(const float* __restrict__ mu,
                                               const float* __restrict__ sig,
                                               const float* __restrict__ w1,
                                               const float* __restrict__ b1) {
    __shared__ float xs[16][256];
    int t = threadIdx.x;
    int nb = blockIdx.x * 16;
    #pragma unroll
    for (int i = 0; i < 16; i++) {
        xs[i][t]       = mu[(nb + i) * HD + t];
        xs[i][128 + t] = sig[(nb + i) * HD + t];
    }
    __syncthreads();
    float acc[16];
    float b = b1[t];
    #pragma unroll
    for (int i = 0; i < 16; i++) acc[i] = b;
    #pragma unroll 4
    for (int k = 0; k < 256; k++) {
        float w = __ldg(&w1[k * HD + t]);
        #pragma unroll
        for (int i = 0; i < 16; i++) acc[i] += xs[i][k] * w;
    }
    #pragma unroll
    for (int i = 0; i < 16; i++) g_A[(nb + i) * HD + t] = acc[i];
}

// ---------------- chain B2 (side stream): edge hidden + tf32 mma layer-2 ----------------
#define HPAD 132
__global__ void __launch_bounds__(128) k_edge(const int* __restrict__ ei,
                                              const float* __restrict__ dist,
                                              const float* __restrict__ conf,
                                              const float* __restrict__ ang,
                                              const float* __restrict__ dep,
                                              const float* __restrict__ w1,
                                              const float* __restrict__ w2,
                                              const float* __restrict__ b2) {
    __shared__ float hid[64 * HPAD];
    int t = threadIdx.x;
    int eb = blockIdx.x * 64;

    float wf0 = w1[(256) * HD + t];
    float wf1 = w1[(257) * HD + t];
    float wf2 = w1[(258) * HD + t];
    float wf3 = w1[(259) * HD + t];
    #pragma unroll 4
    for (int x = 0; x < 64; x++) {
        int e = eb + x;
        int s = ei[e];
        float v = g_A[s * HD + t]
                + dist[e] * wf0 + conf[e] * wf1 + ang[e] * wf2 + dep[e] * wf3;
        hid[x * HPAD + t] = fmaxf(v, 0.0f);
    }
    __syncthreads();

    int warp = t >> 5;
    int lane = t & 31;
    int gid = lane >> 2;
    int tig = lane & 3;
    int n0 = warp * 32;

    float c[4][4][4];
    #pragma unroll
    for (int mt = 0; mt < 4; mt++)
        #pragma unroll
        for (int nt = 0; nt < 4; nt++)
            #pragma unroll
            for (int q = 0; q < 4; q++) c[mt][nt][q] = 0.0f;

    const uint32_t* hidu = (const uint32_t*)hid;

    #pragma unroll 2
    for (int kt = 0; kt < 16; kt++) {
        int k0 = kt * 8;
        uint32_t b0[4], b1[4];
        #pragma unroll
        for (int nt = 0; nt < 4; nt++) {
            int n = n0 + nt * 8 + gid;
            b0[nt] = __float_as_uint(__ldg(&w2[(k0 + tig) * HD + n]));
            b1[nt] = __float_as_uint(__ldg(&w2[(k0 + tig + 4) * HD + n]));
        }
        uint32_t a0[4], a1[4], a2[4], a3[4];
        #pragma unroll
        for (int mt = 0; mt < 4; mt++) {
            int r0 = mt * 16 + gid;
            a0[mt] = hidu[r0 * HPAD + k0 + tig];
            a1[mt] = hidu[(r0 + 8) * HPAD + k0 + tig];
            a2[mt] = hidu[r0 * HPAD + k0 + tig + 4];
            a3[mt] = hidu[(r0 + 8) * HPAD + k0 + tig + 4];
        }
        #pragma unroll
        for (int mt = 0; mt < 4; mt++)
            #pragma unroll
            for (int nt = 0; nt < 4; nt++) {
                asm volatile(
                    "mma.sync.aligned.m16n8k8.row.col.f32.tf32.tf32.f32 "
                    "{%0,%1,%2,%3}, {%4,%5,%6,%7}, {%8,%9}, {%0,%1,%2,%3};"
                    : "+f"(c[mt][nt][0]), "+f"(c[mt][nt][1]),
                      "+f"(c[mt][nt][2]), "+f"(c[mt][nt][3])
                    : "r"(a0[mt]), "r"(a1[mt]), "r"(a2[mt]), "r"(a3[mt]),
                      "r"(b0[nt]), "r"(b1[nt]));
            }
    }

    #pragma unroll
    for (int nt = 0; nt < 4; nt++) {
        int n = n0 + nt * 8 + 2 * tig;
        float bb0 = __ldg(&b2[n]);
        float bb1 = __ldg(&b2[n + 1]);
        #pragma unroll
        for (int mt = 0; mt < 4; mt++) {
            int e0 = eb + mt * 16 + gid;
            int e1 = e0 + 8;
            float2 v0 = make_float2(c[mt][nt][0] + bb0, c[mt][nt][1] + bb1);
            float2 v1 = make_float2(c[mt][nt][2] + bb0, c[mt][nt][3] + bb1);
            *(float2*)&g_wm[e0 * HD + n] = v0;
            *(float2*)&g_wm[e1 * HD + n] = v1;
        }
    }
}

// ---------------- join: aggregation (weighting here) + state cleanup ----------------
__global__ void __launch_bounds__(128) k_agg(const int* __restrict__ ei) {
    int n = blockIdx.x;
    int t = threadIdx.x;

    // cleanup: reset adj entries for edges [16n, 16n+16)  (k_res done)
    if (t < 16) {
        int e = n * 16 + t;
        int s = ei[e], d = ei[NE + e];
        g_adj[s * NN + d] = 0;
    }
    // cleanup: counter arrays (first 32 blocks cover 2 x 2048 ints)
    if (n < 32) {
        int i = n * 128 + t;
        if (i < 2048) g_wcnt_src[i] = 0;
        else          g_cnt_dst[i - 2048] = 0;
    }

    int cnt = g_cnt_dst[n];
    int base = n * CAP;
    float acc = 0.0f, ws = 0.0f, rs = 0.0f;
    for (int i = 0; i < cnt; i++) {
        int e = g_in_edge[base + i];
        float w = g_wgt[e];
        acc += g_wm[e * HD + t] * w;
        ws  += w;
        rs  += g_res[e];
    }
    g_agg[n * HD + t] = acc / fmaxf(ws, 1e-8f);
    if (t == 0) g_meanr[n] = rs / fmaxf((float)cnt, 1.0f);
}

// ---------------- node MLPs ----------------
__global__ void __launch_bounds__(128) k_node(const float* __restrict__ mu,
                                              const float* __restrict__ muw1, const float* __restrict__ mub1,
                                              const float* __restrict__ muw2, const float* __restrict__ mub2,
                                              const float* __restrict__ sgw1, const float* __restrict__ sgb1,
                                              const float* __restrict__ sgw2, const float* __restrict__ sgb2,
                                              float* __restrict__ out) {
    __shared__ float xs[16][128];
    __shared__ float ys[16][128];
    __shared__ float mr[16];
    int t = threadIdx.x;
    int nb = blockIdx.x * 16;
    #pragma unroll
    for (int i = 0; i < 16; i++) xs[i][t] = g_agg[(nb + i) * HD + t];
    if (t < 16) mr[t] = g_meanr[nb + t];
    __syncthreads();

    float acc[16];

    { float b = mub1[t];
      #pragma unroll
      for (int i = 0; i < 16; i++) acc[i] = b;
      #pragma unroll 4
      for (int k = 0; k < 128; k++) {
          float w = __ldg(&muw1[k * HD + t]);
          #pragma unroll
          for (int i = 0; i < 16; i++) acc[i] += xs[i][k] * w;
      } }
    #pragma unroll
    for (int i = 0; i < 16; i++) ys[i][t] = fmaxf(acc[i], 0.0f);
    __syncthreads();

    { float b = mub2[t];
      #pragma unroll
      for (int i = 0; i < 16; i++) acc[i] = b;
      #pragma unroll 4
      for (int k = 0; k < 128; k++) {
          float w = __ldg(&muw2[k * HD + t]);
          #pragma unroll
          for (int i = 0; i < 16; i++) acc[i] += ys[i][k] * w;
      }
      #pragma unroll
      for (int i = 0; i < 16; i++)
          out[(nb + i) * HD + t] = mu[(nb + i) * HD + t] + acc[i];
    }

    { float b = sgb1[t];
      float wlast = __ldg(&sgw1[128 * HD + t]);
      #pragma unroll
      for (int i = 0; i < 16; i++) acc[i] = b + mr[i] * wlast;
      #pragma unroll 4
      for (int k = 0; k < 128; k++) {
          float w = __ldg(&sgw1[k * HD + t]);
          #pragma unroll
          for (int i = 0; i < 16; i++) acc[i] += xs[i][k] * w;
      } }
    __syncthreads();
    #pragma unroll
    for (int i = 0; i < 16; i++) ys[i][t] = fmaxf(acc[i], 0.0f);
    __syncthreads();

    { float b = sgb2[t];
      #pragma unroll
      for (int i = 0; i < 16; i++) acc[i] = b;
      #pragma unroll 4
      for (int k = 0; k < 128; k++) {
          float w = __ldg(&sgw2[k * HD + t]);
          #pragma unroll
          for (int i = 0; i < 16; i++) acc[i] += ys[i][k] * w;
      }
      #pragma unroll
      for (int i = 0; i < 16; i++) {
          float x = acc[i];
          float sp = fmaxf(x, 0.0f) + log1pf(expf(-fabsf(x)));
          out[NN * HD + (nb + i) * HD + t] = sp;
      } }
}

// ---------------- launch ----------------
extern "C" void kernel_launch(void* const* d_in, const int* in_sizes, int n_in,
                              void* d_out, int out_size) {
    const float* mu    = (const float*)d_in[0];
    const float* sigma = (const float*)d_in[1];
    const int*   ei    = (const int*)d_in[2];
    const float* dist  = (const float*)d_in[3];
    const float* conf  = (const float*)d_in[4];
    const float* ang   = (const float*)d_in[5];
    const float* dep   = (const float*)d_in[6];
    const float* msgw1 = (const float*)d_in[7];
    const float* msgb1 = (const float*)d_in[8];
    const float* msgw2 = (const float*)d_in[9];
    const float* msgb2 = (const float*)d_in[10];
    const float* muw1  = (const float*)d_in[11];
    const float* mub1  = (const float*)d_in[12];
    const float* muw2  = (const float*)d_in[13];
    const float* mub2  = (const float*)d_in[14];
    const float* sgw1  = (const float*)d_in[15];
    const float* sgb1  = (const float*)d_in[16];
    const float* sgw2  = (const float*)d_in[17];
    const float* sgb2  = (const float*)d_in[18];
    float* out = (float*)d_out;
    float* out_res = out + 2 * NN * HD;

    static cudaStream_t s_side = nullptr;
    static cudaEvent_t  s_fork = nullptr, s_join = nullptr;
    if (s_side == nullptr) {
        cudaStreamCreateWithFlags(&s_side, cudaStreamNonBlocking);
        cudaEventCreateWithFlags(&s_fork, cudaEventDisableTiming);
        cudaEventCreateWithFlags(&s_join, cudaEventDisableTiming);
    }

    // fork chain B: nodeA -> edge (independent of adjacency chain)
    cudaEventRecord(s_fork, 0);
    cudaStreamWaitEvent(s_side, s_fork, 0);
    k_nodeA<<<NN / 16, 128, 0, s_side>>>(mu, sigma, msgw1, msgb1);
    k_edge<<<NE / 64, 128, 0, s_side>>>(ei, dist, conf, ang, dep, msgw1, msgw2, msgb2);
    cudaEventRecord(s_join, s_side);

    // chain A: adjacency / residuals (no scan, bucket CSRs)
    k_scatcnt<<<NE / 256, 256>>>(ei);
    k_fill<<<NE / 256, 256>>>(ei, dist);
    k_res<<<NE / 8, 256>>>(ei, dist, out_res);

    // join, then aggregate + node MLPs
    cudaStreamWaitEvent(0, s_join, 0);
    k_agg<<<NN, 128>>>(ei);
    k_node<<<NN / 16, 128>>>(mu, muw1, mub1, muw2, mub2, sgw1, sgb1, sgw2, sgb2, out);
}